// round 7
// baseline (speedup 1.0000x reference)
#include <cuda_runtime.h>
#include <cuda_bf16.h>
#include <cstdint>

#define B_   32
#define S_   4096
#define T_   8192
#define DIN  128
#define DT   256
#define M_   (B_ * T_)        // 262144
#define TILE_M 64
#define NBLK  (M_ / TILE_M)   // 4096
#define NCTA  296             // 2 per SM x 148

// ---------------- device-global tables (no runtime allocation) -------------
__device__ float    g_slens[B_];
__device__ float    g_w[4];
__device__ uint16_t g_whi[DT * DT];     // W bf16 hi, [k][n] row-major
__device__ uint16_t g_wlo[DT * DT];     // W bf16 lo
__device__ uint32_t g_pehi[T_ * 64];    // pos_emb packed bf16x2 hi, [t][pair]
__device__ uint32_t g_pelo[T_ * 64];

// ---------------- smem layout (swizzled, pitch 512) ------------------------
#define OFF_A_HI 0              // 64 rows x 512 B
#define OFF_A_LO 32768
#define OFF_B0   65536
#define B_MAT    8192           // 16 rows x 512 (one matrix, one K16 chunk)
#define B_STAGE  16384          // hi + lo
#define SMEM_TOTAL (OFF_B0 + 3 * B_STAGE)   // 114688 -> 2 CTAs/SM
// epilogue LN-partial overlay lives in the A region (A is dead during the
// epilogue; B stages must stay untouched -- prefetches are in flight there).
#define OFF_PS   OFF_A_HI
#define OFF_PS2  (OFF_A_HI + 1024)

// ---------------- asm helpers ----------------------------------------------
__device__ __forceinline__ uint32_t smem_u32(const void* p) {
    uint32_t a;
    asm("{ .reg .u64 t; cvta.to.shared.u64 t, %1; cvt.u32.u64 %0, t; }" : "=r"(a) : "l"(p));
    return a;
}
#define CP_ASYNC16(dst, src) \
    asm volatile("cp.async.cg.shared.global [%0], [%1], 16;" :: "r"(dst), "l"(src))
#define CP_COMMIT() asm volatile("cp.async.commit_group;" ::: "memory")
#define CP_WAIT1()  asm volatile("cp.async.wait_group 1;" ::: "memory")

#define LDSM4(r, addr) \
    asm volatile("ldmatrix.sync.aligned.m8n8.x4.shared.b16 {%0,%1,%2,%3}, [%4];" \
        : "=r"((r)[0]), "=r"((r)[1]), "=r"((r)[2]), "=r"((r)[3]) : "r"(addr))
#define LDSM4T(r, addr) \
    asm volatile("ldmatrix.sync.aligned.m8n8.x4.trans.shared.b16 {%0,%1,%2,%3}, [%4];" \
        : "=r"((r)[0]), "=r"((r)[1]), "=r"((r)[2]), "=r"((r)[3]) : "r"(addr))

// NOTE: not volatile -> ptxas is free to schedule/pipeline MMAs.
__device__ __forceinline__ void mma_bf16(float* c, const uint32_t* a, const uint32_t* b) {
    asm("mma.sync.aligned.m16n8k16.row.col.f32.bf16.bf16.f32 "
        "{%0,%1,%2,%3}, {%4,%5,%6,%7}, {%8,%9}, {%0,%1,%2,%3};"
        : "+f"(c[0]), "+f"(c[1]), "+f"(c[2]), "+f"(c[3])
        : "r"(a[0]), "r"(a[1]), "r"(a[2]), "r"(a[3]), "r"(b[0]), "r"(b[1]));
}

// packs (x0 -> low half, x1 -> high half)
#define CVT2(result, x0, x1) \
    asm("cvt.rn.satfinite.bf16x2.f32 %0, %1, %2;" : "=r"(result) : "f"(x1), "f"(x0))

__device__ __forceinline__ float gelu_exact(float x) {
    return 0.5f * x * (1.0f + erff(x * 0.70710678118654752440f));
}

// ---------------- kernel 1: s_lens + neighbor softmax ----------------------
__global__ void k_prep(const float* __restrict__ s_mask, const float* __restrict__ nw) {
    int tid = threadIdx.x, w = tid >> 5, lane = tid & 31;
    const float* row = s_mask + (size_t)w * S_;
    float s = 0.f;
    for (int i = lane; i < S_; i += 32) s += row[i];
    #pragma unroll
    for (int o = 16; o; o >>= 1) s += __shfl_xor_sync(0xFFFFFFFFu, s, o);
    if (lane == 0) g_slens[w] = s;
    if (tid == 0) {
        float a = nw[0], b = nw[1], c = nw[2];
        float m = fmaxf(a, fmaxf(b, c));
        float ea = expf(a - m), eb = expf(b - m), ec = expf(c - m);
        float inv = 1.f / (ea + eb + ec);
        g_w[0] = ea * inv; g_w[1] = eb * inv; g_w[2] = ec * inv;
    }
}

// ---------------- kernel 2: pos_emb -> packed bf16x2 hi/lo [t][64] ---------
__global__ void k_posemb(const float* __restrict__ w1, const float* __restrict__ b1,
                         const float* __restrict__ w2, const float* __restrict__ b2) {
    __shared__ float h[64];
    int t = blockIdx.x, tid = threadIdx.x;   // 128 threads
    float pos = (float)t * (1.0f / (float)(T_ - 1));
    if (tid < 64) h[tid] = gelu_exact(pos * w1[tid] + b1[tid]);
    __syncthreads();
    float acc = b2[tid];
    #pragma unroll 16
    for (int j = 0; j < 64; j++) acc = fmaf(h[j], w2[j * DIN + tid], acc);
    float x1 = __shfl_down_sync(0xFFFFFFFFu, acc, 1);
    if ((tid & 1) == 0) {
        uint32_t ph; CVT2(ph, acc, x1);
        float l0 = acc - __uint_as_float(ph << 16);
        float l1 = x1  - __uint_as_float(ph & 0xFFFF0000u);
        uint32_t pl; CVT2(pl, l0, l1);
        g_pehi[t * 64 + (tid >> 1)] = ph;
        g_pelo[t * 64 + (tid >> 1)] = pl;
    }
}

// ---------------- kernel 3: W -> bf16 hi/lo [k][n] -------------------------
__global__ void k_wsplit(const float* __restrict__ W) {
    int idx = blockIdx.x * 256 + threadIdx.x;   // 65536
    float x = W[idx];
    __nv_bfloat16 hb = __float2bfloat16(x);
    float hf = __bfloat162float(hb);
    __nv_bfloat16 lb = __float2bfloat16(x - hf);
    __nv_bfloat16_raw hr = hb, lr = lb;
    g_whi[idx] = hr.x;
    g_wlo[idx] = lr.x;
}

// ---------------- B chunk loader: K=16, swizzled, cp.async -----------------
__device__ __forceinline__ void load_B_chunk(uint32_t sb, int stage, int chunk, int tid) {
    uint32_t dst = sb + OFF_B0 + stage * B_STAGE;
    const char* shi = (const char*)(g_whi + chunk * 16 * DT);
    const char* slo = (const char*)(g_wlo + chunk * 16 * DT);
    #pragma unroll
    for (int i = 0; i < 4; i++) {
        int f   = tid + 256 * i;           // 0..1023
        int mat = f >> 9;                  // 0=hi, 1=lo
        int r   = (f >> 5) & 15;           // K row within chunk
        int c   = f & 31;                  // 16B segment
        const char* src = (mat ? slo : shi) + (size_t)r * 512 + c * 16;
        CP_ASYNC16(dst + mat * B_MAT + r * 512 + ((c ^ (r & 7)) << 4), src);
    }
}

// ---------------- kernel 4: persistent fused gather+GEMM+epilogue ----------
__global__ void __launch_bounds__(256, 2)
k_main(const float* __restrict__ emb, const float* __restrict__ s_mask,
       const float* __restrict__ tmask,
       const float* __restrict__ bias, const float* __restrict__ lng,
       const float* __restrict__ lnb, float* __restrict__ out) {
    extern __shared__ char smem[];
    uint32_t sb = smem_u32(smem);
    int tid = threadIdx.x, wid = tid >> 5, lane = tid & 31;
    int wm = wid >> 2;        // 0..1 : M half (32 rows)
    int wn = wid & 3;         // 0..3 : N quarter (64 cols)

    // ---- ldmatrix lane addressing (block-invariant) ----
    int xr = (lane & 7) + ((lane >> 3) & 1) * 8;   // 0..15
    int xg = lane >> 4;                            // 0..1
    int a_row = wm * 32 + xr;
    uint32_t a_base = sb + OFF_A_HI + a_row * 512;
    uint32_t a_xor  = ((a_row & 7) << 4) ^ (xg * 16);
    uint32_t b_base = xr * 512;
    uint32_t b_xor  = (xr & 7) << 4;
    int b_col = wn * 128 + xg * 16;
    uint32_t co[4];
    #pragma unroll
    for (int p = 0; p < 4; p++) co[p] = ((uint32_t)(b_col + p * 32) ^ b_xor) + b_base;

    // epilogue params (block-invariant): registers once per CTA
    float2 bia[8], gg[8], be[8];
    #pragma unroll
    for (int nt = 0; nt < 8; nt++) {
        int c = wn * 64 + nt * 8 + 2 * (lane & 3);
        bia[nt] = *(const float2*)&bias[c];
        gg[nt]  = *(const float2*)&lng[c];
        be[nt]  = *(const float2*)&lnb[c];
    }

    // ---- B pipeline: prime stages 0,1 with chunks 0,1; never drains -------
    load_B_chunk(sb, 0, 0, tid);
    CP_COMMIT();
    load_B_chunk(sb, 1, 1, tid);
    CP_COMMIT();
    int st = 0;                // consume stage; prefetch goes to (st+2)%3

    for (int blk = blockIdx.x; blk < NBLK; blk += NCTA) {
        int m0 = blk * TILE_M;
        int t0 = m0 & (T_ - 1);
        int b  = m0 >> 13;

        // early exit: t_mask is a prefix mask -> whole block exactly zero.
        // Does not touch the B pipeline (no consume, no prefetch).
        if (tmask[m0] == 0.f) {
            float4 z = make_float4(0.f, 0.f, 0.f, 0.f);
            float4* o4 = (float4*)(out + (size_t)m0 * DT);
            #pragma unroll
            for (int i = 0; i < 16; i++) o4[tid + 256 * i] = z;
            continue;
        }

        // barrier: previous epilogue's PS reads (overlaid on A region) must
        // complete before this block's A-prod overwrites it.
        __syncthreads();

        // ---- produce A tile (64 x 256) as bf16 hi/lo, swizzled ----
        {
            float slen = g_slens[b];
            float wv0 = g_w[0], wv1 = g_w[1], wv2 = g_w[2];
            const float* mrow = s_mask + (size_t)b * S_;
            // phase 1: indices + mask-weighted coefficients (24 scalar LDG in flight)
            int   ip[8], ic[8], in_[8];
            float w0a[8], w1a[8], w2a[8];
            #pragma unroll
            for (int i = 0; i < 8; i++) {
                int t = t0 + wid * 8 + i;
                float pos = (float)t * (1.0f / (float)(T_ - 1));
                float sp  = pos * (slen - 1.0f);
                int curr = (int)sp;
                ip[i] = max(curr - 1, 0);
                ic[i] = curr;
                in_[i] = min(curr + 1, S_ - 1);
            }
            #pragma unroll
            for (int i = 0; i < 8; i++) {
                w0a[i] = wv0 * mrow[ip[i]];
                w1a[i] = wv1 * mrow[ic[i]];
                w2a[i] = wv2 * mrow[in_[i]];
            }
            // phase 2: vector loads + blend + split + store
            #pragma unroll 2
            for (int i = 0; i < 8; i++) {
                int row = wid * 8 + i;
                int t = t0 + row;
                const float4* ep = (const float4*)(emb + ((size_t)b * S_ + ip[i]) * DIN);
                const float4* ec = (const float4*)(emb + ((size_t)b * S_ + ic[i]) * DIN);
                const float4* en = (const float4*)(emb + ((size_t)b * S_ + in_[i]) * DIN);
                float4 vp = ep[lane], vc = ec[lane], vn = en[lane];
                float w0 = w0a[i], w1 = w1a[i], w2 = w2a[i];
                float v0 = w0 * vp.x + w1 * vc.x + w2 * vn.x;
                float v1 = w0 * vp.y + w1 * vc.y + w2 * vn.y;
                float v2 = w0 * vp.z + w1 * vc.z + w2 * vn.z;
                float v3 = w0 * vp.w + w1 * vc.w + w2 * vn.w;
                uint32_t h0; CVT2(h0, v0, v1);
                uint32_t h1; CVT2(h1, v2, v3);
                float l00 = v0 - __uint_as_float(h0 << 16);
                float l01 = v1 - __uint_as_float(h0 & 0xFFFF0000u);
                float l10 = v2 - __uint_as_float(h1 << 16);
                float l11 = v3 - __uint_as_float(h1 & 0xFFFF0000u);
                uint32_t q0; CVT2(q0, l00, l01);
                uint32_t q1; CVT2(q1, l10, l11);
                uint32_t rbase = row * 512;
                uint32_t rxor  = (row & 7) << 4;
                uint32_t o1 = rbase + ((8 * lane) ^ rxor);
                *(uint2*)(smem + OFF_A_HI + o1) = make_uint2(h0, h1);
                *(uint2*)(smem + OFF_A_LO + o1) = make_uint2(q0, q1);
                uint2 peh = *(const uint2*)(g_pehi + (size_t)t * 64 + 2 * lane);
                uint2 pel = *(const uint2*)(g_pelo + (size_t)t * 64 + 2 * lane);
                uint32_t o2 = rbase + ((256 + 8 * lane) ^ rxor);
                *(uint2*)(smem + OFF_A_HI + o2) = peh;
                *(uint2*)(smem + OFF_A_LO + o2) = pel;
            }
        }

        float acc[2][8][4];
        #pragma unroll
        for (int mt = 0; mt < 2; mt++)
            #pragma unroll
            for (int nt = 0; nt < 8; nt++)
                #pragma unroll
                for (int c = 0; c < 4; c++) acc[mt][nt][c] = 0.f;

        // ---- mainloop: 16 chunks of K=16; pipeline continues across blocks
        for (int kc = 0; kc < 16; kc++) {
            CP_WAIT1();
            __syncthreads();
            {   // prefetch chunk (kc+2) mod 16 -- B is block-invariant, so at
                // kc=14,15 this is already the NEXT block's chunks 0,1.
                int nst = st + 2; if (nst >= 3) nst -= 3;
                load_B_chunk(sb, nst, (kc + 2) & 15, tid);
                CP_COMMIT();
            }
            uint32_t bstage = sb + OFF_B0 + st * B_STAGE;
            uint32_t aoff = ((uint32_t)(kc * 32)) ^ a_xor;
            uint32_t Ahi[2][4], Alo[2][4];
            LDSM4(Ahi[0], a_base + aoff);
            LDSM4(Ahi[1], a_base + 16 * 512 + aoff);
            LDSM4(Alo[0], a_base + (OFF_A_LO - OFF_A_HI) + aoff);
            LDSM4(Alo[1], a_base + (OFF_A_LO - OFF_A_HI) + 16 * 512 + aoff);
            #pragma unroll
            for (int p = 0; p < 4; p++) {
                uint32_t Bhi[4], Blo[4];
                LDSM4T(Bhi, bstage + co[p]);
                LDSM4T(Blo, bstage + B_MAT + co[p]);
                mma_bf16(acc[0][2 * p],     Ahi[0], &Bhi[0]);
                mma_bf16(acc[0][2 * p + 1], Ahi[0], &Bhi[2]);
                mma_bf16(acc[1][2 * p],     Ahi[1], &Bhi[0]);
                mma_bf16(acc[1][2 * p + 1], Ahi[1], &Bhi[2]);
                mma_bf16(acc[0][2 * p],     Ahi[0], &Blo[0]);
                mma_bf16(acc[0][2 * p + 1], Ahi[0], &Blo[2]);
                mma_bf16(acc[1][2 * p],     Ahi[1], &Blo[0]);
                mma_bf16(acc[1][2 * p + 1], Ahi[1], &Blo[2]);
                mma_bf16(acc[0][2 * p],     Alo[0], &Bhi[0]);
                mma_bf16(acc[0][2 * p + 1], Alo[0], &Bhi[2]);
                mma_bf16(acc[1][2 * p],     Alo[1], &Bhi[0]);
                mma_bf16(acc[1][2 * p + 1], Alo[1], &Bhi[2]);
            }
            st = (st == 2) ? 0 : st + 1;
        }
        __syncthreads();   // A region now dead -> PS overlay becomes valid

        // ---- epilogue: gelu + layernorm + mask ----
        float* ps   = (float*)(smem + OFF_PS);
        float* ps2  = (float*)(smem + OFF_PS2);

        #pragma unroll
        for (int mt = 0; mt < 2; mt++) {
            float sA = 0.f, s2A = 0.f, sB = 0.f, s2B = 0.f;
            #pragma unroll
            for (int nt = 0; nt < 8; nt++) {
                float v0 = gelu_exact(acc[mt][nt][0] + bia[nt].x);
                float v1 = gelu_exact(acc[mt][nt][1] + bia[nt].y);
                float v2 = gelu_exact(acc[mt][nt][2] + bia[nt].x);
                float v3 = gelu_exact(acc[mt][nt][3] + bia[nt].y);
                acc[mt][nt][0] = v0; acc[mt][nt][1] = v1;
                acc[mt][nt][2] = v2; acc[mt][nt][3] = v3;
                sA += v0 + v1; s2A += v0 * v0 + v1 * v1;
                sB += v2 + v3; s2B += v2 * v2 + v3 * v3;
            }
            #pragma unroll
            for (int o = 1; o <= 2; o <<= 1) {
                sA  += __shfl_xor_sync(0xFFFFFFFFu, sA,  o);
                s2A += __shfl_xor_sync(0xFFFFFFFFu, s2A, o);
                sB  += __shfl_xor_sync(0xFFFFFFFFu, sB,  o);
                s2B += __shfl_xor_sync(0xFFFFFFFFu, s2B, o);
            }
            if ((lane & 3) == 0) {
                int rA = wm * 32 + mt * 16 + (lane >> 2);
                ps[rA * 4 + wn]  = sA;  ps2[rA * 4 + wn]  = s2A;
                ps[(rA + 8) * 4 + wn] = sB; ps2[(rA + 8) * 4 + wn] = s2B;
            }
        }
        __syncthreads();

        #pragma unroll
        for (int mt = 0; mt < 2; mt++) {
            int rA = wm * 32 + mt * 16 + (lane >> 2);
            int rB = rA + 8;
            float tsA  = ps[rA * 4] + ps[rA * 4 + 1] + ps[rA * 4 + 2] + ps[rA * 4 + 3];
            float ts2A = ps2[rA * 4] + ps2[rA * 4 + 1] + ps2[rA * 4 + 2] + ps2[rA * 4 + 3];
            float tsB  = ps[rB * 4] + ps[rB * 4 + 1] + ps[rB * 4 + 2] + ps[rB * 4 + 3];
            float ts2B = ps2[rB * 4] + ps2[rB * 4 + 1] + ps2[rB * 4 + 2] + ps2[rB * 4 + 3];
            float muA = tsA * (1.f / 256.f);
            float muB = tsB * (1.f / 256.f);
            float invA = rsqrtf(ts2A * (1.f / 256.f) - muA * muA + 1e-5f);
            float invB = rsqrtf(ts2B * (1.f / 256.f) - muB * muB + 1e-5f);
            float mkA = tmask[m0 + rA];
            float mkB = tmask[m0 + rB];
            #pragma unroll
            for (int nt = 0; nt < 8; nt++) {
                int c = wn * 64 + nt * 8 + 2 * (lane & 3);
                float2 o1, o2;
                o1.x = ((acc[mt][nt][0] - muA) * invA * gg[nt].x + be[nt].x) * mkA;
                o1.y = ((acc[mt][nt][1] - muA) * invA * gg[nt].y + be[nt].y) * mkA;
                o2.x = ((acc[mt][nt][2] - muB) * invB * gg[nt].x + be[nt].x) * mkB;
                o2.y = ((acc[mt][nt][3] - muB) * invB * gg[nt].y + be[nt].y) * mkB;
                *(float2*)(out + (size_t)(m0 + rA) * DT + c) = o1;
                *(float2*)(out + (size_t)(m0 + rB) * DT + c) = o2;
            }
        }
    }
}

// ---------------- launch ---------------------------------------------------
extern "C" void kernel_launch(void* const* d_in, const int* in_sizes, int n_in,
                              void* d_out, int out_size) {
    const float* student_emb = (const float*)d_in[0];
    const float* s_mask      = (const float*)d_in[1];
    const float* t_mask      = (const float*)d_in[2];
    int p = (in_sizes[3] == 64) ? 3 : 4;
    const float* pe_w1 = (const float*)d_in[p + 0];
    const float* pe_b1 = (const float*)d_in[p + 1];
    const float* pe_w2 = (const float*)d_in[p + 2];
    const float* pe_b2 = (const float*)d_in[p + 3];
    const float* pt_w  = (const float*)d_in[p + 4];
    const float* pt_b  = (const float*)d_in[p + 5];
    const float* ln_g  = (const float*)d_in[p + 6];
    const float* ln_b  = (const float*)d_in[p + 7];
    const float* nw    = (const float*)d_in[p + 8];
    float* out = (float*)d_out;

    cudaFuncSetAttribute(k_main, cudaFuncAttributeMaxDynamicSharedMemorySize, SMEM_TOTAL);

    k_prep<<<1, 1024>>>(s_mask, nw);
    k_posemb<<<T_, 128>>>(pe_w1, pe_b1, pe_w2, pe_b2);
    k_wsplit<<<DT * DT / 256, 256>>>(pt_w);
    k_main<<<NCTA, 256, SMEM_TOTAL>>>(student_emb, s_mask, t_mask,
                                      pt_b, ln_g, ln_b, out);
}

// round 8
// speedup vs baseline: 1.4754x; 1.4754x over previous
#include <cuda_runtime.h>
#include <cuda_fp16.h>
#include <cstdint>

#define B_   32
#define S_   4096
#define T_   8192
#define DIN  128
#define DT   256
#define M_   (B_ * T_)        // 262144
#define TILE_M 64
#define NBLK  (M_ / TILE_M)   // 4096

// ---------------- device-global tables (no runtime allocation) -------------
__device__ float    g_slens[B_];
__device__ float    g_w[4];
__device__ uint16_t g_wh[DT * DT];      // W fp16 (rounded), [k][n] row-major
__device__ uint32_t g_pehi[T_ * 64];    // pos_emb packed fp16x2 hi, [t][pair]
__device__ uint32_t g_pelo[T_ * 64];    // fp16x2 lo residual

// ---------------- smem layout (swizzled, pitch 512) ------------------------
#define OFF_A_HI 0              // 64 rows x 512 B (fp16: 256 cols)
#define OFF_A_LO 32768
#define OFF_B0   65536
#define B_STAGE  8192           // 16 rows x 512 B (single fp16 matrix per chunk)
#define SMEM_TOTAL (OFF_B0 + 3 * B_STAGE)   // 90112 -> 2 CTAs/SM
// epilogue overlays (valid after final mainloop barrier; pipeline drained):
#define OFF_PS   OFF_B0
#define OFF_PS2  (OFF_B0 + 1024)

// ---------------- asm helpers ----------------------------------------------
__device__ __forceinline__ uint32_t smem_u32(const void* p) {
    uint32_t a;
    asm("{ .reg .u64 t; cvta.to.shared.u64 t, %1; cvt.u32.u64 %0, t; }" : "=r"(a) : "l"(p));
    return a;
}
#define CP_ASYNC16(dst, src) \
    asm volatile("cp.async.cg.shared.global [%0], [%1], 16;" :: "r"(dst), "l"(src))
#define CP_COMMIT() asm volatile("cp.async.commit_group;" ::: "memory")
#define CP_WAIT0()  asm volatile("cp.async.wait_group 0;" ::: "memory")
#define CP_WAIT1()  asm volatile("cp.async.wait_group 1;" ::: "memory")

#define LDSM4(r, addr) \
    asm volatile("ldmatrix.sync.aligned.m8n8.x4.shared.b16 {%0,%1,%2,%3}, [%4];" \
        : "=r"((r)[0]), "=r"((r)[1]), "=r"((r)[2]), "=r"((r)[3]) : "r"(addr))
#define LDSM4T(r, addr) \
    asm volatile("ldmatrix.sync.aligned.m8n8.x4.trans.shared.b16 {%0,%1,%2,%3}, [%4];" \
        : "=r"((r)[0]), "=r"((r)[1]), "=r"((r)[2]), "=r"((r)[3]) : "r"(addr))

// NOTE: not volatile -> ptxas is free to schedule/pipeline MMAs.
__device__ __forceinline__ void mma_f16(float* c, const uint32_t* a, const uint32_t* b) {
    asm("mma.sync.aligned.m16n8k16.row.col.f32.f16.f16.f32 "
        "{%0,%1,%2,%3}, {%4,%5,%6,%7}, {%8,%9}, {%0,%1,%2,%3};"
        : "+f"(c[0]), "+f"(c[1]), "+f"(c[2]), "+f"(c[3])
        : "r"(a[0]), "r"(a[1]), "r"(a[2]), "r"(a[3]), "r"(b[0]), "r"(b[1]));
}

__device__ __forceinline__ uint32_t h2u(__half2 h) {
    uint32_t u; *(__half2*)&u = h; return u;
}

__device__ __forceinline__ float gelu_exact(float x) {
    return 0.5f * x * (1.0f + erff(x * 0.70710678118654752440f));
}

// ---------------- kernel 1: s_lens + neighbor softmax ----------------------
__global__ void k_prep(const float* __restrict__ s_mask, const float* __restrict__ nw) {
    int tid = threadIdx.x, w = tid >> 5, lane = tid & 31;
    const float* row = s_mask + (size_t)w * S_;
    float s = 0.f;
    for (int i = lane; i < S_; i += 32) s += row[i];
    #pragma unroll
    for (int o = 16; o; o >>= 1) s += __shfl_xor_sync(0xFFFFFFFFu, s, o);
    if (lane == 0) g_slens[w] = s;
    if (tid == 0) {
        float a = nw[0], b = nw[1], c = nw[2];
        float m = fmaxf(a, fmaxf(b, c));
        float ea = expf(a - m), eb = expf(b - m), ec = expf(c - m);
        float inv = 1.f / (ea + eb + ec);
        g_w[0] = ea * inv; g_w[1] = eb * inv; g_w[2] = ec * inv;
    }
}

// ---------------- kernel 2: pos_emb -> packed fp16x2 hi/lo [t][64] ---------
__global__ void k_posemb(const float* __restrict__ w1, const float* __restrict__ b1,
                         const float* __restrict__ w2, const float* __restrict__ b2) {
    __shared__ float h[64];
    int t = blockIdx.x, tid = threadIdx.x;   // 128 threads
    float pos = (float)t * (1.0f / (float)(T_ - 1));
    if (tid < 64) h[tid] = gelu_exact(pos * w1[tid] + b1[tid]);
    __syncthreads();
    float acc = b2[tid];
    #pragma unroll 16
    for (int j = 0; j < 64; j++) acc = fmaf(h[j], w2[j * DIN + tid], acc);
    float x1 = __shfl_down_sync(0xFFFFFFFFu, acc, 1);
    if ((tid & 1) == 0) {
        __half2 hh = __floats2half2_rn(acc, x1);
        float l0 = acc - __low2float(hh);
        float l1 = x1  - __high2float(hh);
        __half2 ll = __floats2half2_rn(l0, l1);
        int c = tid >> 1;
        g_pehi[t * 64 + c] = h2u(hh);
        g_pelo[t * 64 + c] = h2u(ll);
    }
}

// ---------------- kernel 3: W -> fp16 (single, rounded) [k][n] -------------
__global__ void k_wsplit(const float* __restrict__ W) {
    int idx = blockIdx.x * 256 + threadIdx.x;   // 65536
    __half h = __float2half_rn(W[idx]);
    g_wh[idx] = *(uint16_t*)&h;
}

// ---------------- B chunk loader: K=16, swizzled, cp.async (8KB) -----------
__device__ __forceinline__ void load_B_chunk(uint32_t sb, int stage, int chunk, int tid) {
    uint32_t dst = sb + OFF_B0 + stage * B_STAGE;
    const char* src0 = (const char*)(g_wh + chunk * 16 * DT);
    #pragma unroll
    for (int i = 0; i < 2; i++) {
        int f = tid + 256 * i;             // 0..511
        int r = f >> 5;                    // K row within chunk (0..15)
        int c = f & 31;                    // 16B segment
        CP_ASYNC16(dst + r * 512 + ((c ^ (r & 7)) << 4), src0 + (size_t)r * 512 + c * 16);
    }
}

// ---------------- kernel 4: fused gather + fp16-split GEMM + epilogue ------
__global__ void __launch_bounds__(256, 2)
k_main(const float* __restrict__ emb, const float* __restrict__ s_mask,
       const float* __restrict__ tmask,
       const float* __restrict__ bias, const float* __restrict__ lng,
       const float* __restrict__ lnb, float* __restrict__ out) {
    extern __shared__ char smem[];
    uint32_t sb = smem_u32(smem);
    int tid = threadIdx.x, wid = tid >> 5, lane = tid & 31;
    int wm = wid >> 2;        // 0..1 : M half (32 rows)
    int wn = wid & 3;         // 0..3 : N quarter (64 cols)
    int m0 = blockIdx.x * TILE_M;
    int t0 = m0 & (T_ - 1);   // all 64 rows share batch b
    int b  = m0 >> 13;

    // early exit: t_mask is a prefix mask -> whole block exactly zero.
    if (tmask[m0] == 0.f) {
        float4 z = make_float4(0.f, 0.f, 0.f, 0.f);
        float4* o4 = (float4*)(out + (size_t)m0 * DT);
        #pragma unroll
        for (int i = 0; i < 16; i++) o4[tid + 256 * i] = z;
        return;
    }

    // prefetch B chunks 0,1 (stages 0,1)
    load_B_chunk(sb, 0, 0, tid);
    CP_COMMIT();
    load_B_chunk(sb, 1, 1, tid);
    CP_COMMIT();

    // ---- produce A tile (64 x 256) as fp16 hi+lo, swizzled ----------------
    {
        float slen = g_slens[b];
        float wv0 = g_w[0], wv1 = g_w[1], wv2 = g_w[2];
        const float* mrow = s_mask + (size_t)b * S_;
        // phase 1: indices + mask-weighted coefficients (scalar LDGs batched)
        int   ip[8], ic[8], in_[8];
        float w0a[8], w1a[8], w2a[8];
        #pragma unroll
        for (int i = 0; i < 8; i++) {
            int t = t0 + wid * 8 + i;
            float pos = (float)t * (1.0f / (float)(T_ - 1));
            float sp  = pos * (slen - 1.0f);
            int curr = (int)sp;
            ip[i] = max(curr - 1, 0);
            ic[i] = curr;
            in_[i] = min(curr + 1, S_ - 1);
        }
        #pragma unroll
        for (int i = 0; i < 8; i++) {
            w0a[i] = wv0 * mrow[ip[i]];
            w1a[i] = wv1 * mrow[ic[i]];
            w2a[i] = wv2 * mrow[in_[i]];
        }
        // phase 2: vector loads + blend + fp16 split + store
        #pragma unroll 2
        for (int i = 0; i < 8; i++) {
            int row = wid * 8 + i;
            int t = t0 + row;
            const float4* ep = (const float4*)(emb + ((size_t)b * S_ + ip[i]) * DIN);
            const float4* ec = (const float4*)(emb + ((size_t)b * S_ + ic[i]) * DIN);
            const float4* en = (const float4*)(emb + ((size_t)b * S_ + in_[i]) * DIN);
            float4 vp = ep[lane], vc = ec[lane], vn = en[lane];
            float w0 = w0a[i], w1 = w1a[i], w2 = w2a[i];
            float v0 = w0 * vp.x + w1 * vc.x + w2 * vn.x;
            float v1 = w0 * vp.y + w1 * vc.y + w2 * vn.y;
            float v2 = w0 * vp.z + w1 * vc.z + w2 * vn.z;
            float v3 = w0 * vp.w + w1 * vc.w + w2 * vn.w;
            __half2 hh0 = __floats2half2_rn(v0, v1);
            __half2 hh1 = __floats2half2_rn(v2, v3);
            __half2 ll0 = __floats2half2_rn(v0 - __low2float(hh0), v1 - __high2float(hh0));
            __half2 ll1 = __floats2half2_rn(v2 - __low2float(hh1), v3 - __high2float(hh1));
            uint32_t rbase = row * 512;
            uint32_t rxor  = (row & 7) << 4;
            uint32_t o1 = rbase + ((8 * lane) ^ rxor);
            *(uint2*)(smem + OFF_A_HI + o1) = make_uint2(h2u(hh0), h2u(hh1));
            *(uint2*)(smem + OFF_A_LO + o1) = make_uint2(h2u(ll0), h2u(ll1));
            uint2 peh = *(const uint2*)(g_pehi + (size_t)t * 64 + 2 * lane);
            uint2 pel = *(const uint2*)(g_pelo + (size_t)t * 64 + 2 * lane);
            uint32_t o2 = rbase + ((256 + 8 * lane) ^ rxor);
            *(uint2*)(smem + OFF_A_HI + o2) = peh;
            *(uint2*)(smem + OFF_A_LO + o2) = pel;
        }
    }

    // ---- ldmatrix lane addressing ----
    int xr = (lane & 7) + ((lane >> 3) & 1) * 8;   // 0..15
    int xg = lane >> 4;                            // 0..1
    int a_row = wm * 32 + xr;
    uint32_t a_base = sb + OFF_A_HI + a_row * 512;
    uint32_t a_xor  = ((a_row & 7) << 4) ^ (xg * 16);
    uint32_t b_base = xr * 512;
    uint32_t b_xor  = (xr & 7) << 4;
    int b_col = wn * 128 + xg * 16;
    uint32_t co[4];
    #pragma unroll
    for (int p = 0; p < 4; p++) co[p] = ((uint32_t)(b_col + p * 32) ^ b_xor) + b_base;

    float acc[2][8][4];
    #pragma unroll
    for (int mt = 0; mt < 2; mt++)
        #pragma unroll
        for (int nt = 0; nt < 8; nt++)
            #pragma unroll
            for (int c = 0; c < 4; c++) acc[mt][nt][c] = 0.f;

    // ---- mainloop: 16 chunks of K=16, 3-stage pipeline --------------------
    int st = 0;
    for (int kc = 0; kc < 16; kc++) {
        if (kc == 15) { CP_WAIT0(); } else { CP_WAIT1(); }
        __syncthreads();
        if (kc < 14) {
            int nst = st + 2; if (nst >= 3) nst -= 3;
            load_B_chunk(sb, nst, kc + 2, tid);
            CP_COMMIT();
        }
        uint32_t bstage = sb + OFF_B0 + st * B_STAGE;
        uint32_t aoff = ((uint32_t)(kc * 32)) ^ a_xor;
        uint32_t Ahi[2][4], Alo[2][4];
        LDSM4(Ahi[0], a_base + aoff);
        LDSM4(Ahi[1], a_base + 16 * 512 + aoff);
        LDSM4(Alo[0], a_base + (OFF_A_LO - OFF_A_HI) + aoff);
        LDSM4(Alo[1], a_base + (OFF_A_LO - OFF_A_HI) + 16 * 512 + aoff);
        #pragma unroll
        for (int p = 0; p < 4; p++) {
            uint32_t Bf[4];
            LDSM4T(Bf, bstage + co[p]);
            // 2 products (A_hi + A_lo) x single fp16 B; dep distance 4
            mma_f16(acc[0][2 * p],     Ahi[0], &Bf[0]);
            mma_f16(acc[0][2 * p + 1], Ahi[0], &Bf[2]);
            mma_f16(acc[1][2 * p],     Ahi[1], &Bf[0]);
            mma_f16(acc[1][2 * p + 1], Ahi[1], &Bf[2]);
            mma_f16(acc[0][2 * p],     Alo[0], &Bf[0]);
            mma_f16(acc[0][2 * p + 1], Alo[0], &Bf[2]);
            mma_f16(acc[1][2 * p],     Alo[1], &Bf[0]);
            mma_f16(acc[1][2 * p + 1], Alo[1], &Bf[2]);
        }
        st = (st == 2) ? 0 : st + 1;
    }
    __syncthreads();   // pipeline drained -> B region free for LN overlay

    // ---- epilogue: gelu + layernorm + mask (params straight from gmem) ----
    float* ps   = (float*)(smem + OFF_PS);
    float* ps2  = (float*)(smem + OFF_PS2);

    float2 bia[8], gg[8], be[8];
    #pragma unroll
    for (int nt = 0; nt < 8; nt++) {
        int c = wn * 64 + nt * 8 + 2 * (lane & 3);
        bia[nt] = *(const float2*)&bias[c];
        gg[nt]  = *(const float2*)&lng[c];
        be[nt]  = *(const float2*)&lnb[c];
    }

    #pragma unroll
    for (int mt = 0; mt < 2; mt++) {
        float sA = 0.f, s2A = 0.f, sB = 0.f, s2B = 0.f;
        #pragma unroll
        for (int nt = 0; nt < 8; nt++) {
            float v0 = gelu_exact(acc[mt][nt][0] + bia[nt].x);
            float v1 = gelu_exact(acc[mt][nt][1] + bia[nt].y);
            float v2 = gelu_exact(acc[mt][nt][2] + bia[nt].x);
            float v3 = gelu_exact(acc[mt][nt][3] + bia[nt].y);
            acc[mt][nt][0] = v0; acc[mt][nt][1] = v1;
            acc[mt][nt][2] = v2; acc[mt][nt][3] = v3;
            sA += v0 + v1; s2A += v0 * v0 + v1 * v1;
            sB += v2 + v3; s2B += v2 * v2 + v3 * v3;
        }
        #pragma unroll
        for (int o = 1; o <= 2; o <<= 1) {
            sA  += __shfl_xor_sync(0xFFFFFFFFu, sA,  o);
            s2A += __shfl_xor_sync(0xFFFFFFFFu, s2A, o);
            sB  += __shfl_xor_sync(0xFFFFFFFFu, sB,  o);
            s2B += __shfl_xor_sync(0xFFFFFFFFu, s2B, o);
        }
        if ((lane & 3) == 0) {
            int rA = wm * 32 + mt * 16 + (lane >> 2);
            ps[rA * 4 + wn]  = sA;  ps2[rA * 4 + wn]  = s2A;
            ps[(rA + 8) * 4 + wn] = sB; ps2[(rA + 8) * 4 + wn] = s2B;
        }
    }
    __syncthreads();

    #pragma unroll
    for (int mt = 0; mt < 2; mt++) {
        int rA = wm * 32 + mt * 16 + (lane >> 2);
        int rB = rA + 8;
        float tsA  = ps[rA * 4] + ps[rA * 4 + 1] + ps[rA * 4 + 2] + ps[rA * 4 + 3];
        float ts2A = ps2[rA * 4] + ps2[rA * 4 + 1] + ps2[rA * 4 + 2] + ps2[rA * 4 + 3];
        float tsB  = ps[rB * 4] + ps[rB * 4 + 1] + ps[rB * 4 + 2] + ps[rB * 4 + 3];
        float ts2B = ps2[rB * 4] + ps2[rB * 4 + 1] + ps2[rB * 4 + 2] + ps2[rB * 4 + 3];
        float muA = tsA * (1.f / 256.f);
        float muB = tsB * (1.f / 256.f);
        float invA = rsqrtf(ts2A * (1.f / 256.f) - muA * muA + 1e-5f);
        float invB = rsqrtf(ts2B * (1.f / 256.f) - muB * muB + 1e-5f);
        float mkA = tmask[m0 + rA];
        float mkB = tmask[m0 + rB];
        #pragma unroll
        for (int nt = 0; nt < 8; nt++) {
            int c = wn * 64 + nt * 8 + 2 * (lane & 3);
            float2 o1, o2;
            o1.x = ((acc[mt][nt][0] - muA) * invA * gg[nt].x + be[nt].x) * mkA;
            o1.y = ((acc[mt][nt][1] - muA) * invA * gg[nt].y + be[nt].y) * mkA;
            o2.x = ((acc[mt][nt][2] - muB) * invB * gg[nt].x + be[nt].x) * mkB;
            o2.y = ((acc[mt][nt][3] - muB) * invB * gg[nt].y + be[nt].y) * mkB;
            *(float2*)(out + (size_t)(m0 + rA) * DT + c) = o1;
            *(float2*)(out + (size_t)(m0 + rB) * DT + c) = o2;
        }
    }
}

// ---------------- launch ---------------------------------------------------
extern "C" void kernel_launch(void* const* d_in, const int* in_sizes, int n_in,
                              void* d_out, int out_size) {
    const float* student_emb = (const float*)d_in[0];
    const float* s_mask      = (const float*)d_in[1];
    const float* t_mask      = (const float*)d_in[2];
    int p = (in_sizes[3] == 64) ? 3 : 4;
    const float* pe_w1 = (const float*)d_in[p + 0];
    const float* pe_b1 = (const float*)d_in[p + 1];
    const float* pe_w2 = (const float*)d_in[p + 2];
    const float* pe_b2 = (const float*)d_in[p + 3];
    const float* pt_w  = (const float*)d_in[p + 4];
    const float* pt_b  = (const float*)d_in[p + 5];
    const float* ln_g  = (const float*)d_in[p + 6];
    const float* ln_b  = (const float*)d_in[p + 7];
    const float* nw    = (const float*)d_in[p + 8];
    float* out = (float*)d_out;

    cudaFuncSetAttribute(k_main, cudaFuncAttributeMaxDynamicSharedMemorySize, SMEM_TOTAL);

    k_prep<<<1, 1024>>>(s_mask, nw);
    k_posemb<<<T_, 128>>>(pe_w1, pe_b1, pe_w2, pe_b2);
    k_wsplit<<<DT * DT / 256, 256>>>(pt_w);
    k_main<<<NBLK, 256, SMEM_TOTAL>>>(student_emb, s_mask, t_mask,
                                      pt_b, ln_g, ln_b, out);
}

// round 9
// speedup vs baseline: 1.7333x; 1.1748x over previous
#include <cuda_runtime.h>
#include <cuda_fp16.h>
#include <cstdint>

#define B_   32
#define S_   4096
#define T_   8192
#define DIN  128
#define DT   256
#define M_   (B_ * T_)        // 262144
#define TILE_M 64
#define NBLK  (M_ / TILE_M)   // 4096

// ---------------- device-global tables (no runtime allocation) -------------
__device__ float    g_slens[B_];
__device__ float    g_w[4];
__device__ uint16_t g_wh[DT * DT];      // W fp16 (rounded), [k][n] row-major
__device__ uint32_t g_peh[T_ * 64];     // pos_emb packed fp16x2, [t][pair]

// ---------------- smem layout (swizzled, pitch 512) ------------------------
#define OFF_A    0              // 64 rows x 512 B (fp16: 256 cols)
#define OFF_B0   32768
#define B_STAGE  16384          // 32 rows x 512 B (one K32 chunk)
#define SMEM_TOTAL (OFF_B0 + 3 * B_STAGE)   // 81920 -> 2 CTAs/SM
// epilogue overlays (valid after final mainloop barrier; pipeline drained):
#define OFF_PS   OFF_B0
#define OFF_PS2  (OFF_B0 + 1024)

// ---------------- asm helpers ----------------------------------------------
__device__ __forceinline__ uint32_t smem_u32(const void* p) {
    uint32_t a;
    asm("{ .reg .u64 t; cvta.to.shared.u64 t, %1; cvt.u32.u64 %0, t; }" : "=r"(a) : "l"(p));
    return a;
}
#define CP_ASYNC16(dst, src) \
    asm volatile("cp.async.cg.shared.global [%0], [%1], 16;" :: "r"(dst), "l"(src))
#define CP_COMMIT() asm volatile("cp.async.commit_group;" ::: "memory")
#define CP_WAIT0()  asm volatile("cp.async.wait_group 0;" ::: "memory")
#define CP_WAIT1()  asm volatile("cp.async.wait_group 1;" ::: "memory")

#define LDSM4(r, addr) \
    asm volatile("ldmatrix.sync.aligned.m8n8.x4.shared.b16 {%0,%1,%2,%3}, [%4];" \
        : "=r"((r)[0]), "=r"((r)[1]), "=r"((r)[2]), "=r"((r)[3]) : "r"(addr))
#define LDSM4T(r, addr) \
    asm volatile("ldmatrix.sync.aligned.m8n8.x4.trans.shared.b16 {%0,%1,%2,%3}, [%4];" \
        : "=r"((r)[0]), "=r"((r)[1]), "=r"((r)[2]), "=r"((r)[3]) : "r"(addr))

// NOTE: not volatile -> ptxas is free to schedule/pipeline MMAs.
__device__ __forceinline__ void mma_f16(float* c, const uint32_t* a, const uint32_t* b) {
    asm("mma.sync.aligned.m16n8k16.row.col.f32.f16.f16.f32 "
        "{%0,%1,%2,%3}, {%4,%5,%6,%7}, {%8,%9}, {%0,%1,%2,%3};"
        : "+f"(c[0]), "+f"(c[1]), "+f"(c[2]), "+f"(c[3])
        : "r"(a[0]), "r"(a[1]), "r"(a[2]), "r"(a[3]), "r"(b[0]), "r"(b[1]));
}

__device__ __forceinline__ uint32_t h2u(__half2 h) {
    uint32_t u; *(__half2*)&u = h; return u;
}

__device__ __forceinline__ float gelu_exact(float x) {
    return 0.5f * x * (1.0f + erff(x * 0.70710678118654752440f));
}

// ---------------- kernel 1: s_lens + neighbor softmax ----------------------
__global__ void k_prep(const float* __restrict__ s_mask, const float* __restrict__ nw) {
    int tid = threadIdx.x, w = tid >> 5, lane = tid & 31;
    const float* row = s_mask + (size_t)w * S_;
    float s = 0.f;
    for (int i = lane; i < S_; i += 32) s += row[i];
    #pragma unroll
    for (int o = 16; o; o >>= 1) s += __shfl_xor_sync(0xFFFFFFFFu, s, o);
    if (lane == 0) g_slens[w] = s;
    if (tid == 0) {
        float a = nw[0], b = nw[1], c = nw[2];
        float m = fmaxf(a, fmaxf(b, c));
        float ea = expf(a - m), eb = expf(b - m), ec = expf(c - m);
        float inv = 1.f / (ea + eb + ec);
        g_w[0] = ea * inv; g_w[1] = eb * inv; g_w[2] = ec * inv;
    }
}

// ---------------- kernel 2: pos_emb -> packed fp16x2 [t][64] ---------------
__global__ void k_posemb(const float* __restrict__ w1, const float* __restrict__ b1,
                         const float* __restrict__ w2, const float* __restrict__ b2) {
    __shared__ float h[64];
    int t = blockIdx.x, tid = threadIdx.x;   // 128 threads
    float pos = (float)t * (1.0f / (float)(T_ - 1));
    if (tid < 64) h[tid] = gelu_exact(pos * w1[tid] + b1[tid]);
    __syncthreads();
    float acc = b2[tid];
    #pragma unroll 16
    for (int j = 0; j < 64; j++) acc = fmaf(h[j], w2[j * DIN + tid], acc);
    float x1 = __shfl_down_sync(0xFFFFFFFFu, acc, 1);
    if ((tid & 1) == 0)
        g_peh[t * 64 + (tid >> 1)] = h2u(__floats2half2_rn(acc, x1));
}

// ---------------- kernel 3: W -> fp16 (rounded) [k][n] ---------------------
__global__ void k_wsplit(const float* __restrict__ W) {
    int idx = blockIdx.x * 256 + threadIdx.x;   // 65536
    __half h = __float2half_rn(W[idx]);
    g_wh[idx] = *(uint16_t*)&h;
}

// ---------------- B chunk loader: K=32, swizzled, cp.async (16KB) ----------
__device__ __forceinline__ void load_B_chunk(uint32_t sb, int stage, int chunk, int tid) {
    uint32_t dst = sb + OFF_B0 + stage * B_STAGE;
    const char* src0 = (const char*)(g_wh + chunk * 32 * DT);
    #pragma unroll
    for (int i = 0; i < 4; i++) {
        int f = tid + 256 * i;             // 0..1023
        int r = f >> 5;                    // K row within chunk (0..31)
        int c = f & 31;                    // 16B segment
        CP_ASYNC16(dst + r * 512 + ((c ^ (r & 7)) << 4), src0 + (size_t)r * 512 + c * 16);
    }
}

// ---------------- kernel 4: fused gather + fp16 GEMM + epilogue ------------
__global__ void __launch_bounds__(256, 2)
k_main(const float* __restrict__ emb, const float* __restrict__ s_mask,
       const float* __restrict__ tmask,
       const float* __restrict__ bias, const float* __restrict__ lng,
       const float* __restrict__ lnb, float* __restrict__ out) {
    extern __shared__ char smem[];
    uint32_t sb = smem_u32(smem);
    int tid = threadIdx.x, wid = tid >> 5, lane = tid & 31;
    int wm = wid >> 2;        // 0..1 : M half (32 rows)
    int wn = wid & 3;         // 0..3 : N quarter (64 cols)
    int m0 = blockIdx.x * TILE_M;
    int t0 = m0 & (T_ - 1);   // all 64 rows share batch b
    int b  = m0 >> 13;

    // early exit: t_mask is a prefix mask -> whole block exactly zero.
    if (tmask[m0] == 0.f) {
        float4 z = make_float4(0.f, 0.f, 0.f, 0.f);
        float4* o4 = (float4*)(out + (size_t)m0 * DT);
        #pragma unroll
        for (int i = 0; i < 16; i++) o4[tid + 256 * i] = z;
        return;
    }

    // prefetch B chunks 0,1 (stages 0,1)
    load_B_chunk(sb, 0, 0, tid);
    CP_COMMIT();
    load_B_chunk(sb, 1, 1, tid);
    CP_COMMIT();

    // ---- produce A tile (64 x 256) as fp16, swizzled ----------------------
    {
        float slen = g_slens[b];
        float wv0 = g_w[0], wv1 = g_w[1], wv2 = g_w[2];
        const float* mrow = s_mask + (size_t)b * S_;
        // phase 1: indices + mask-weighted coefficients (scalar LDGs batched)
        int   ip[8], ic[8], in_[8];
        float w0a[8], w1a[8], w2a[8];
        #pragma unroll
        for (int i = 0; i < 8; i++) {
            int t = t0 + wid * 8 + i;
            float pos = (float)t * (1.0f / (float)(T_ - 1));
            float sp  = pos * (slen - 1.0f);
            int curr = (int)sp;
            ip[i] = max(curr - 1, 0);
            ic[i] = curr;
            in_[i] = min(curr + 1, S_ - 1);
        }
        #pragma unroll
        for (int i = 0; i < 8; i++) {
            w0a[i] = wv0 * mrow[ip[i]];
            w1a[i] = wv1 * mrow[ic[i]];
            w2a[i] = wv2 * mrow[in_[i]];
        }
        // phase 2: vector loads + blend + fp16 round + store
        #pragma unroll 2
        for (int i = 0; i < 8; i++) {
            int row = wid * 8 + i;
            int t = t0 + row;
            const float4* ep = (const float4*)(emb + ((size_t)b * S_ + ip[i]) * DIN);
            const float4* ec = (const float4*)(emb + ((size_t)b * S_ + ic[i]) * DIN);
            const float4* en = (const float4*)(emb + ((size_t)b * S_ + in_[i]) * DIN);
            float4 vp = ep[lane], vc = ec[lane], vn = en[lane];
            float w0 = w0a[i], w1 = w1a[i], w2 = w2a[i];
            float v0 = w0 * vp.x + w1 * vc.x + w2 * vn.x;
            float v1 = w0 * vp.y + w1 * vc.y + w2 * vn.y;
            float v2 = w0 * vp.z + w1 * vc.z + w2 * vn.z;
            float v3 = w0 * vp.w + w1 * vc.w + w2 * vn.w;
            __half2 hh0 = __floats2half2_rn(v0, v1);
            __half2 hh1 = __floats2half2_rn(v2, v3);
            uint32_t rbase = row * 512;
            uint32_t rxor  = (row & 7) << 4;
            uint32_t o1 = rbase + ((8 * lane) ^ rxor);
            *(uint2*)(smem + OFF_A + o1) = make_uint2(h2u(hh0), h2u(hh1));
            uint2 peh = *(const uint2*)(g_peh + (size_t)t * 64 + 2 * lane);
            uint32_t o2 = rbase + ((256 + 8 * lane) ^ rxor);
            *(uint2*)(smem + OFF_A + o2) = peh;
        }
    }

    // ---- ldmatrix lane addressing ----
    int xr = (lane & 7) + ((lane >> 3) & 1) * 8;   // 0..15
    int xg = lane >> 4;                            // 0..1
    int a_row = wm * 32 + xr;
    uint32_t a_base = sb + OFF_A + a_row * 512;
    uint32_t a_xor  = ((a_row & 7) << 4) ^ (xg * 16);
    uint32_t b_base = xr * 512;
    uint32_t b_xor  = (xr & 7) << 4;
    int b_col = wn * 128 + xg * 16;
    uint32_t co[4];
    #pragma unroll
    for (int p = 0; p < 4; p++) co[p] = ((uint32_t)(b_col + p * 32) ^ b_xor) + b_base;

    float acc[2][8][4];
    #pragma unroll
    for (int mt = 0; mt < 2; mt++)
        #pragma unroll
        for (int nt = 0; nt < 8; nt++)
            #pragma unroll
            for (int c = 0; c < 4; c++) acc[mt][nt][c] = 0.f;

    // ---- mainloop: 8 chunks of K=32, 3-stage pipeline ---------------------
    int st = 0;
    for (int kc = 0; kc < 8; kc++) {
        if (kc == 7) { CP_WAIT0(); } else { CP_WAIT1(); }
        __syncthreads();
        if (kc < 6) {
            int nst = st + 2; if (nst >= 3) nst -= 3;
            load_B_chunk(sb, nst, kc + 2, tid);
            CP_COMMIT();
        }
        uint32_t bstage = sb + OFF_B0 + st * B_STAGE;
        #pragma unroll
        for (int kk = 0; kk < 2; kk++) {
            uint32_t aoff = ((uint32_t)(kc * 64 + kk * 32)) ^ a_xor;
            uint32_t A0[4], A1[4];
            LDSM4(A0, a_base + aoff);
            LDSM4(A1, a_base + 16 * 512 + aoff);
            uint32_t bk = bstage + kk * 16 * 512;
            #pragma unroll
            for (int p = 0; p < 4; p++) {
                uint32_t Bf[4];
                LDSM4T(Bf, bk + co[p]);
                mma_f16(acc[0][2 * p],     A0, &Bf[0]);
                mma_f16(acc[0][2 * p + 1], A0, &Bf[2]);
                mma_f16(acc[1][2 * p],     A1, &Bf[0]);
                mma_f16(acc[1][2 * p + 1], A1, &Bf[2]);
            }
        }
        st = (st == 2) ? 0 : st + 1;
    }
    __syncthreads();   // pipeline drained -> B region free for LN overlay

    // ---- epilogue: gelu + layernorm + mask (params straight from gmem) ----
    float* ps   = (float*)(smem + OFF_PS);
    float* ps2  = (float*)(smem + OFF_PS2);

    float2 bia[8], gg[8], be[8];
    #pragma unroll
    for (int nt = 0; nt < 8; nt++) {
        int c = wn * 64 + nt * 8 + 2 * (lane & 3);
        bia[nt] = *(const float2*)&bias[c];
        gg[nt]  = *(const float2*)&lng[c];
        be[nt]  = *(const float2*)&lnb[c];
    }

    #pragma unroll
    for (int mt = 0; mt < 2; mt++) {
        float sA = 0.f, s2A = 0.f, sB = 0.f, s2B = 0.f;
        #pragma unroll
        for (int nt = 0; nt < 8; nt++) {
            float v0 = gelu_exact(acc[mt][nt][0] + bia[nt].x);
            float v1 = gelu_exact(acc[mt][nt][1] + bia[nt].y);
            float v2 = gelu_exact(acc[mt][nt][2] + bia[nt].x);
            float v3 = gelu_exact(acc[mt][nt][3] + bia[nt].y);
            acc[mt][nt][0] = v0; acc[mt][nt][1] = v1;
            acc[mt][nt][2] = v2; acc[mt][nt][3] = v3;
            sA += v0 + v1; s2A += v0 * v0 + v1 * v1;
            sB += v2 + v3; s2B += v2 * v2 + v3 * v3;
        }
        #pragma unroll
        for (int o = 1; o <= 2; o <<= 1) {
            sA  += __shfl_xor_sync(0xFFFFFFFFu, sA,  o);
            s2A += __shfl_xor_sync(0xFFFFFFFFu, s2A, o);
            sB  += __shfl_xor_sync(0xFFFFFFFFu, sB,  o);
            s2B += __shfl_xor_sync(0xFFFFFFFFu, s2B, o);
        }
        if ((lane & 3) == 0) {
            int rA = wm * 32 + mt * 16 + (lane >> 2);
            ps[rA * 4 + wn]  = sA;  ps2[rA * 4 + wn]  = s2A;
            ps[(rA + 8) * 4 + wn] = sB; ps2[(rA + 8) * 4 + wn] = s2B;
        }
    }
    __syncthreads();

    #pragma unroll
    for (int mt = 0; mt < 2; mt++) {
        int rA = wm * 32 + mt * 16 + (lane >> 2);
        int rB = rA + 8;
        float tsA  = ps[rA * 4] + ps[rA * 4 + 1] + ps[rA * 4 + 2] + ps[rA * 4 + 3];
        float ts2A = ps2[rA * 4] + ps2[rA * 4 + 1] + ps2[rA * 4 + 2] + ps2[rA * 4 + 3];
        float tsB  = ps[rB * 4] + ps[rB * 4 + 1] + ps[rB * 4 + 2] + ps[rB * 4 + 3];
        float ts2B = ps2[rB * 4] + ps2[rB * 4 + 1] + ps2[rB * 4 + 2] + ps2[rB * 4 + 3];
        float muA = tsA * (1.f / 256.f);
        float muB = tsB * (1.f / 256.f);
        float invA = rsqrtf(ts2A * (1.f / 256.f) - muA * muA + 1e-5f);
        float invB = rsqrtf(ts2B * (1.f / 256.f) - muB * muB + 1e-5f);
        float mkA = tmask[m0 + rA];
        float mkB = tmask[m0 + rB];
        #pragma unroll
        for (int nt = 0; nt < 8; nt++) {
            int c = wn * 64 + nt * 8 + 2 * (lane & 3);
            float2 o1, o2;
            o1.x = ((acc[mt][nt][0] - muA) * invA * gg[nt].x + be[nt].x) * mkA;
            o1.y = ((acc[mt][nt][1] - muA) * invA * gg[nt].y + be[nt].y) * mkA;
            o2.x = ((acc[mt][nt][2] - muB) * invB * gg[nt].x + be[nt].x) * mkB;
            o2.y = ((acc[mt][nt][3] - muB) * invB * gg[nt].y + be[nt].y) * mkB;
            *(float2*)(out + (size_t)(m0 + rA) * DT + c) = o1;
            *(float2*)(out + (size_t)(m0 + rB) * DT + c) = o2;
        }
    }
}

// ---------------- launch ---------------------------------------------------
extern "C" void kernel_launch(void* const* d_in, const int* in_sizes, int n_in,
                              void* d_out, int out_size) {
    const float* student_emb = (const float*)d_in[0];
    const float* s_mask      = (const float*)d_in[1];
    const float* t_mask      = (const float*)d_in[2];
    int p = (in_sizes[3] == 64) ? 3 : 4;
    const float* pe_w1 = (const float*)d_in[p + 0];
    const float* pe_b1 = (const float*)d_in[p + 1];
    const float* pe_w2 = (const float*)d_in[p + 2];
    const float* pe_b2 = (const float*)d_in[p + 3];
    const float* pt_w  = (const float*)d_in[p + 4];
    const float* pt_b  = (const float*)d_in[p + 5];
    const float* ln_g  = (const float*)d_in[p + 6];
    const float* ln_b  = (const float*)d_in[p + 7];
    const float* nw    = (const float*)d_in[p + 8];
    float* out = (float*)d_out;

    cudaFuncSetAttribute(k_main, cudaFuncAttributeMaxDynamicSharedMemorySize, SMEM_TOTAL);

    k_prep<<<1, 1024>>>(s_mask, nw);
    k_posemb<<<T_, 128>>>(pe_w1, pe_b1, pe_w2, pe_b2);
    k_wsplit<<<DT * DT / 256, 256>>>(pt_w);
    k_main<<<NBLK, 256, SMEM_TOTAL>>>(student_emb, s_mask, t_mask,
                                      pt_b, ln_g, ln_b, out);
}